// round 1
// baseline (speedup 1.0000x reference)
#include <cuda_runtime.h>
#include <math.h>

#define B_  4
#define L_  1024
#define D_  1024
#define H_  16
#define HD_ 64
#define D3_ 3072

// Scratch (allocation-free rule: device globals)
__device__ float g_qkv[(size_t)B_ * L_ * D3_];   // [B,L,3D]  q|k|v
__device__ float g_y[(size_t)B_ * L_ * D_];      // [B,L,D]   attention output (heads merged)

// ---------------------------------------------------------------------------
// SGEMM (NT): C[m,n] = sum_k A[m,k] * B[n,k]; A row-major [M,K], B row-major [N,K].
// 128x128 tile, BK=8, 256 threads, 8x8 per thread, register prefetch.
// M,N,K must be multiples of 128/128/8 (true for all three calls).
// ---------------------------------------------------------------------------
__global__ __launch_bounds__(256) void sgemm_nt(const float* __restrict__ A,
                                                const float* __restrict__ Bm,
                                                float* __restrict__ C,
                                                int M, int N, int K) {
    __shared__ float As[8][128];
    __shared__ float Bs[8][128];
    const int tid = threadIdx.x;
    const int tx = tid & 15, ty = tid >> 4;
    const int bm = blockIdx.y * 128, bn = blockIdx.x * 128;
    const int lr = tid >> 1;          // 0..127 row within tile
    const int lk = (tid & 1) * 4;     // 0 or 4

    const float* Ag = A  + (size_t)(bm + lr) * K + lk;
    const float* Bg = Bm + (size_t)(bn + lr) * K + lk;
    float4 ap = *(const float4*)Ag;
    float4 bp = *(const float4*)Bg;

    float acc[8][8];
#pragma unroll
    for (int i = 0; i < 8; ++i)
#pragma unroll
        for (int j = 0; j < 8; ++j) acc[i][j] = 0.f;

    const int nk = K >> 3;
    for (int kt = 0; kt < nk; ++kt) {
        As[lk + 0][lr] = ap.x; As[lk + 1][lr] = ap.y;
        As[lk + 2][lr] = ap.z; As[lk + 3][lr] = ap.w;
        Bs[lk + 0][lr] = bp.x; Bs[lk + 1][lr] = bp.y;
        Bs[lk + 2][lr] = bp.z; Bs[lk + 3][lr] = bp.w;
        __syncthreads();
        if (kt + 1 < nk) {
            ap = *(const float4*)(Ag + (size_t)(kt + 1) * 8);
            bp = *(const float4*)(Bg + (size_t)(kt + 1) * 8);
        }
#pragma unroll
        for (int k = 0; k < 8; ++k) {
            float4 a0 = *(const float4*)&As[k][ty * 4];
            float4 a1 = *(const float4*)&As[k][64 + ty * 4];
            float4 b0 = *(const float4*)&Bs[k][tx * 4];
            float4 b1 = *(const float4*)&Bs[k][64 + tx * 4];
            float ar[8] = {a0.x, a0.y, a0.z, a0.w, a1.x, a1.y, a1.z, a1.w};
            float br[8] = {b0.x, b0.y, b0.z, b0.w, b1.x, b1.y, b1.z, b1.w};
#pragma unroll
            for (int i = 0; i < 8; ++i)
#pragma unroll
                for (int j = 0; j < 8; ++j)
                    acc[i][j] = fmaf(ar[i], br[j], acc[i][j]);
        }
        __syncthreads();
    }

#pragma unroll
    for (int i = 0; i < 8; ++i) {
        int row = bm + ((i < 4) ? (ty * 4 + i) : (64 + ty * 4 + (i - 4)));
        float* Cr = C + (size_t)row * N + bn;
        *(float4*)&Cr[tx * 4]      = make_float4(acc[i][0], acc[i][1], acc[i][2], acc[i][3]);
        *(float4*)&Cr[64 + tx * 4] = make_float4(acc[i][4], acc[i][5], acc[i][6], acc[i][7]);
    }
}

// ---------------------------------------------------------------------------
// Dual-path causal flash attention, fp32.
// Grid: (16 row-tiles, B*H=64). Block: 256 threads (16x16), each thread owns a
// 4x4 patch of the 64x64 score tile and a 4x4 patch of the 64-wide output.
// Static shared only (48 KB): three 16 KB buffers reused across phases.
// logits = (Q.K + Qg.Kg) * (1/sqrt(64)) / ln(1024)
// ---------------------------------------------------------------------------
__global__ __launch_bounds__(256) void attn_kernel(const float* __restrict__ qg_in,
                                                   const float* __restrict__ kg_in,
                                                   float* __restrict__ y) {
    __shared__ float bufA[64 * 64];   // operand A, transposed [d][row]
    __shared__ float bufB[64 * 64];   // operand B, transposed [d][col]  /  V as [s][d]
    __shared__ float Ps[64 * 64];     // P tile [row][s]

    const int bh = blockIdx.y;
    const int b  = bh >> 4;
    const int h  = bh & 15;
    const int rt = blockIdx.x;        // row tile index 0..15
    const int tid = threadIdx.x;
    const int tx = tid & 15, ty = tid >> 4;

    const float* qbase  = g_qkv + (size_t)b * L_ * D3_ + h * HD_;
    const float* kbase  = qbase + D_;
    const float* vbase  = qbase + 2 * D_;
    const float* qgbase = qg_in + (size_t)b * L_ * D_ + h * HD_;
    const float* kgbase = kg_in + (size_t)b * L_ * D_ + h * HD_;

    const int ls  = tid >> 2;         // 0..63 (row within 64-row tile)
    const int ld0 = (tid & 3) * 16;   // d start: 0/16/32/48

    float mrow[4], lrow[4], oacc[4][4];
#pragma unroll
    for (int i = 0; i < 4; ++i) {
        mrow[i] = -INFINITY;
        lrow[i] = 0.f;
#pragma unroll
        for (int j = 0; j < 4; ++j) oacc[i][j] = 0.f;
    }

    const float SC = 0.125f / 6.931471805599453f;  // (1/sqrt(hd)) / ln(L)

    for (int t = 0; t <= rt; ++t) {
        float S[4][4];
#pragma unroll
        for (int i = 0; i < 4; ++i)
#pragma unroll
            for (int j = 0; j < 4; ++j) S[i][j] = 0.f;

        // ---- phase 1: x-path scores -------------------------------------
        __syncthreads();   // protect previous iteration's PV reads
        {
            const float* gq = qbase + (size_t)(rt * 64 + ls) * D3_ + ld0;
            const float* gk = kbase + (size_t)(t  * 64 + ls) * D3_ + ld0;
#pragma unroll
            for (int q = 0; q < 4; ++q) {
                float4 va = *(const float4*)(gq + q * 4);
                bufA[(ld0 + q * 4 + 0) * 64 + ls] = va.x;
                bufA[(ld0 + q * 4 + 1) * 64 + ls] = va.y;
                bufA[(ld0 + q * 4 + 2) * 64 + ls] = va.z;
                bufA[(ld0 + q * 4 + 3) * 64 + ls] = va.w;
                float4 vb = *(const float4*)(gk + q * 4);
                bufB[(ld0 + q * 4 + 0) * 64 + ls] = vb.x;
                bufB[(ld0 + q * 4 + 1) * 64 + ls] = vb.y;
                bufB[(ld0 + q * 4 + 2) * 64 + ls] = vb.z;
                bufB[(ld0 + q * 4 + 3) * 64 + ls] = vb.w;
            }
        }
        __syncthreads();
#pragma unroll 4
        for (int d = 0; d < 64; ++d) {
            float4 a = *(const float4*)&bufA[d * 64 + ty * 4];
            float4 c = *(const float4*)&bufB[d * 64 + tx * 4];
            float ar[4] = {a.x, a.y, a.z, a.w};
            float cr[4] = {c.x, c.y, c.z, c.w};
#pragma unroll
            for (int i = 0; i < 4; ++i)
#pragma unroll
                for (int j = 0; j < 4; ++j)
                    S[i][j] = fmaf(ar[i], cr[j], S[i][j]);
        }

        // ---- phase 2: g-path scores -------------------------------------
        __syncthreads();
        {
            const float* gq = qgbase + (size_t)(rt * 64 + ls) * D_ + ld0;
            const float* gk = kgbase + (size_t)(t  * 64 + ls) * D_ + ld0;
#pragma unroll
            for (int q = 0; q < 4; ++q) {
                float4 va = *(const float4*)(gq + q * 4);
                bufA[(ld0 + q * 4 + 0) * 64 + ls] = va.x;
                bufA[(ld0 + q * 4 + 1) * 64 + ls] = va.y;
                bufA[(ld0 + q * 4 + 2) * 64 + ls] = va.z;
                bufA[(ld0 + q * 4 + 3) * 64 + ls] = va.w;
                float4 vb = *(const float4*)(gk + q * 4);
                bufB[(ld0 + q * 4 + 0) * 64 + ls] = vb.x;
                bufB[(ld0 + q * 4 + 1) * 64 + ls] = vb.y;
                bufB[(ld0 + q * 4 + 2) * 64 + ls] = vb.z;
                bufB[(ld0 + q * 4 + 3) * 64 + ls] = vb.w;
            }
        }
        __syncthreads();
#pragma unroll 4
        for (int d = 0; d < 64; ++d) {
            float4 a = *(const float4*)&bufA[d * 64 + ty * 4];
            float4 c = *(const float4*)&bufB[d * 64 + tx * 4];
            float ar[4] = {a.x, a.y, a.z, a.w};
            float cr[4] = {c.x, c.y, c.z, c.w};
#pragma unroll
            for (int i = 0; i < 4; ++i)
#pragma unroll
                for (int j = 0; j < 4; ++j)
                    S[i][j] = fmaf(ar[i], cr[j], S[i][j]);
        }

        // ---- scale + causal mask + online softmax -----------------------
        const bool diag = (t == rt);
#pragma unroll
        for (int i = 0; i < 4; ++i)
#pragma unroll
            for (int j = 0; j < 4; ++j) {
                S[i][j] *= SC;
                if (diag && (tx * 4 + j) > (ty * 4 + i)) S[i][j] = -INFINITY;
            }

#pragma unroll
        for (int i = 0; i < 4; ++i) {
            float mt = fmaxf(fmaxf(S[i][0], S[i][1]), fmaxf(S[i][2], S[i][3]));
#pragma unroll
            for (int off = 8; off >= 1; off >>= 1)
                mt = fmaxf(mt, __shfl_xor_sync(0xffffffffu, mt, off));
            float mnew  = fmaxf(mrow[i], mt);
            float alpha = __expf(mrow[i] - mnew);
            float p0 = __expf(S[i][0] - mnew);
            float p1 = __expf(S[i][1] - mnew);
            float p2 = __expf(S[i][2] - mnew);
            float p3 = __expf(S[i][3] - mnew);
            float ps = p0 + p1 + p2 + p3;
#pragma unroll
            for (int off = 8; off >= 1; off >>= 1)
                ps += __shfl_xor_sync(0xffffffffu, ps, off);
            lrow[i] = lrow[i] * alpha + ps;
            mrow[i] = mnew;
#pragma unroll
            for (int j = 0; j < 4; ++j) oacc[i][j] *= alpha;
            *(float4*)&Ps[(ty * 4 + i) * 64 + tx * 4] = make_float4(p0, p1, p2, p3);
        }

        // ---- phase 3: load V, PV ----------------------------------------
        __syncthreads();   // Ps visible; bufB free (scores done)
        {
            const float* gv = vbase + (size_t)(t * 64 + ls) * D3_ + ld0;
#pragma unroll
            for (int q = 0; q < 4; ++q)
                *(float4*)&bufB[ls * 64 + ld0 + q * 4] = *(const float4*)(gv + q * 4);
        }
        __syncthreads();
#pragma unroll 4
        for (int s = 0; s < 64; ++s) {
            float4 bv = *(const float4*)&bufB[s * 64 + tx * 4];
#pragma unroll
            for (int i = 0; i < 4; ++i) {
                float a = Ps[(ty * 4 + i) * 64 + s];
                oacc[i][0] = fmaf(a, bv.x, oacc[i][0]);
                oacc[i][1] = fmaf(a, bv.y, oacc[i][1]);
                oacc[i][2] = fmaf(a, bv.z, oacc[i][2]);
                oacc[i][3] = fmaf(a, bv.w, oacc[i][3]);
            }
        }
    }

    // ---- normalize + write y[b, row, h*64 + col] ------------------------
    float* yrow = y + ((size_t)b * L_ + (size_t)rt * 64) * D_ + h * HD_;
#pragma unroll
    for (int i = 0; i < 4; ++i) {
        float inv = 1.f / lrow[i];
        int row = ty * 4 + i;
        *(float4*)&yrow[(size_t)row * D_ + tx * 4] =
            make_float4(oacc[i][0] * inv, oacc[i][1] * inv,
                        oacc[i][2] * inv, oacc[i][3] * inv);
    }
}

// ---------------------------------------------------------------------------
extern "C" void kernel_launch(void* const* d_in, const int* in_sizes, int n_in,
                              void* d_out, int out_size) {
    const float* x    = (const float*)d_in[0];
    const float* q_g  = (const float*)d_in[1];
    const float* k_g  = (const float*)d_in[2];
    const float* Wqkv = (const float*)d_in[3];
    const float* Wout = (const float*)d_in[4];
    float* out = (float*)d_out;

    float *qkv, *y;
    cudaGetSymbolAddress((void**)&qkv, g_qkv);
    cudaGetSymbolAddress((void**)&y, g_y);

    // 1) qkv = x @ Wqkv^T : [4096,1024] x [3072,1024]^T -> [4096,3072]
    dim3 g1(D3_ / 128, (B_ * L_) / 128);
    sgemm_nt<<<g1, 256>>>(x, Wqkv, qkv, B_ * L_, D3_, D_);

    // 2) dual-path causal attention -> y [B,L,D]
    attn_kernel<<<dim3(16, B_ * H_), 256>>>(q_g, k_g, y);

    // 3) out = y @ Wout^T : [4096,1024] x [1024,1024]^T -> [4096,1024]
    dim3 g3(D_ / 128, (B_ * L_) / 128);
    sgemm_nt<<<g3, 256>>>(y, Wout, out, B_ * L_, D_, D_);
}